// round 5
// baseline (speedup 1.0000x reference)
#include <cuda_runtime.h>
#include <cstdint>

#define MAX_NODES 100000
#define NREP 8

// One contiguous scratch block so a single captured cudaMemsetAsync clears
// everything (replicated accumulators + scalar partials + done ticket).
struct Scratch {
    float4   acc[NREP][MAX_NODES];  // (c4, s4, deg, pad) per replica
    float    part[2];               // [0] pair_loss_sum, [1] n_pairs
    unsigned done;
};
__device__ Scratch g_s;

__device__ __forceinline__ void red_v4(float4* addr, float a, float b, float c, float d) {
    asm volatile("red.global.add.v4.f32 [%0], {%1, %2, %3, %4};"
                 :: "l"(addr), "f"(a), "f"(b), "f"(c), "f"(d)
                 : "memory");
}

__global__ void edge_kernel(const float* __restrict__ pos,
                            const int*   __restrict__ ei,
                            int E) {
    int e = blockIdx.x * blockDim.x + threadIdx.x;
    if (e >= E) return;
    int rep = (e >> 5) & (NREP - 1);   // per-warp replica -> 8x less L2 per-address contention
    int s = ei[e];
    int t = ei[E + e];
    float2 ps = __ldg((const float2*)pos + s);
    float2 pt = __ldg((const float2*)pos + t);
    float dx = pt.x - ps.x;
    float dy = pt.y - ps.y;
    float nrm = sqrtf(fmaf(dx, dx, dy * dy));
    float inv = 1.0f / fmaxf(nrm, 1e-8f);
    float u = dx * inv, v = dy * inv;
    // cos(2t) = u^2 - v^2 ; sin(2t) = 2uv ; double-angle again for 4t.
    float a = u * u - v * v;
    float b = 2.0f * u * v;
    float c4 = a * a - b * b;
    float s4 = 2.0f * a * b;
    // 4-theta terms are invariant under d -> -d: identical payload to both endpoints.
    red_v4(&g_s.acc[rep][s], c4, s4, 1.0f, 0.0f);
    red_v4(&g_s.acc[rep][t], c4, s4, 1.0f, 0.0f);
}

__global__ void node_kernel(int n, float* __restrict__ out) {
    int i = blockIdx.x * blockDim.x + threadIdx.x;
    float pl = 0.0f, np = 0.0f;
    if (i < n) {
        float c4 = 0.f, s4 = 0.f, k = 0.f;
        #pragma unroll
        for (int r = 0; r < NREP; r++) {
            float4 acc = g_s.acc[r][i];
            c4 += acc.x; s4 += acc.y; k += acc.z;
        }
        // sum_{i<j}(dot^2 - dot^4) = (k^2 - C4^2 - S4^2)/16  (includes the 0.5 pair factor)
        pl = (k * k - (c4 * c4 + s4 * s4)) * 0.0625f;
        np = 0.5f * k * (k - 1.0f);
    }
    #pragma unroll
    for (int o = 16; o > 0; o >>= 1) {
        pl += __shfl_down_sync(0xffffffffu, pl, o);
        np += __shfl_down_sync(0xffffffffu, np, o);
    }
    __shared__ float s_pl[32];
    __shared__ float s_np[32];
    int lane = threadIdx.x & 31;
    int wid  = threadIdx.x >> 5;
    if (lane == 0) { s_pl[wid] = pl; s_np[wid] = np; }
    __syncthreads();
    if (wid == 0) {
        int nw = (blockDim.x + 31) >> 5;
        pl = (lane < nw) ? s_pl[lane] : 0.0f;
        np = (lane < nw) ? s_np[lane] : 0.0f;
        #pragma unroll
        for (int o = 16; o > 0; o >>= 1) {
            pl += __shfl_down_sync(0xffffffffu, pl, o);
            np += __shfl_down_sync(0xffffffffu, np, o);
        }
        if (lane == 0) {
            atomicAdd(&g_s.part[0], pl);
            atomicAdd(&g_s.part[1], np);
            __threadfence();
            unsigned done = atomicAdd(&g_s.done, 1u);
            if (done == gridDim.x - 1) {
                float a = atomicAdd(&g_s.part[0], 0.0f);
                float b = atomicAdd(&g_s.part[1], 0.0f);
                out[0] = a / fmaxf(b, 1.0f);
            }
        }
    }
}

extern "C" void kernel_launch(void* const* d_in, const int* in_sizes, int n_in,
                              void* d_out, int out_size) {
    const float* pos = (const float*)d_in[0];
    const int*   ei  = (const int*)d_in[2];
    int N = in_sizes[0] / 2;      // node_positions: (1, N, 2)
    int E = in_sizes[2] / 2;      // edge_index: (2, E)

    void* scratch_ptr = nullptr;
    cudaGetSymbolAddress(&scratch_ptr, g_s);           // host API, capture-time only
    cudaMemsetAsync(scratch_ptr, 0, sizeof(Scratch));  // captured as a memset node

    const int TB = 256;
    edge_kernel<<<(E + TB - 1) / TB, TB>>>(pos, ei, E);
    node_kernel<<<(N + TB - 1) / TB, TB>>>(N, (float*)d_out);
}

// round 6
// speedup vs baseline: 1.0657x; 1.0657x over previous
#include <cuda_runtime.h>
#include <cstdint>

#define MAX_NODES 100000

// Single contiguous scratch block -> one captured cudaMemsetAsync clears all.
struct Scratch {
    float4   acc[MAX_NODES];  // (c4, s4, deg, pad)
    float    part[2];         // [0] pair_loss_sum, [1] n_pairs
    unsigned done;
};
__device__ Scratch g_s;

__device__ __forceinline__ void red_v4(float4* addr, float a, float b, float c, float d) {
    asm volatile("red.global.add.v4.f32 [%0], {%1, %2, %3, %4};"
                 :: "l"(addr), "f"(a), "f"(b), "f"(c), "f"(d)
                 : "memory");
}

__global__ void edge_kernel(const float* __restrict__ pos,
                            const int*   __restrict__ ei,
                            int E) {
    int e = blockIdx.x * blockDim.x + threadIdx.x;
    if (e >= E) return;
    int s = ei[e];
    int t = ei[E + e];
    float2 ps = __ldg((const float2*)pos + s);
    float2 pt = __ldg((const float2*)pos + t);
    float dx = pt.x - ps.x;
    float dy = pt.y - ps.y;
    float nrm = sqrtf(fmaf(dx, dx, dy * dy));
    float inv = 1.0f / fmaxf(nrm, 1e-8f);
    float u = dx * inv, v = dy * inv;
    // cos(2t) = u^2 - v^2 ; sin(2t) = 2uv ; double-angle again for 4t.
    float a = u * u - v * v;
    float b = 2.0f * u * v;
    float c4 = a * a - b * b;
    float s4 = 2.0f * a * b;
    // 4-theta terms are invariant under d -> -d: identical payload to both endpoints.
    red_v4(&g_s.acc[s], c4, s4, 1.0f, 0.0f);
    red_v4(&g_s.acc[t], c4, s4, 1.0f, 0.0f);
}

__global__ void node_kernel(int n, float* __restrict__ out) {
    int i = blockIdx.x * blockDim.x + threadIdx.x;
    float pl = 0.0f, np = 0.0f;
    if (i < n) {
        float4 acc = g_s.acc[i];
        float k = acc.z;
        // sum_{i<j}(dot^2 - dot^4) = (k^2 - C4^2 - S4^2)/16  (includes the 0.5 pair factor)
        pl = (k * k - (acc.x * acc.x + acc.y * acc.y)) * 0.0625f;
        np = 0.5f * k * (k - 1.0f);
    }
    #pragma unroll
    for (int o = 16; o > 0; o >>= 1) {
        pl += __shfl_down_sync(0xffffffffu, pl, o);
        np += __shfl_down_sync(0xffffffffu, np, o);
    }
    __shared__ float s_pl[32];
    __shared__ float s_np[32];
    int lane = threadIdx.x & 31;
    int wid  = threadIdx.x >> 5;
    if (lane == 0) { s_pl[wid] = pl; s_np[wid] = np; }
    __syncthreads();
    if (wid == 0) {
        int nw = (blockDim.x + 31) >> 5;
        pl = (lane < nw) ? s_pl[lane] : 0.0f;
        np = (lane < nw) ? s_np[lane] : 0.0f;
        #pragma unroll
        for (int o = 16; o > 0; o >>= 1) {
            pl += __shfl_down_sync(0xffffffffu, pl, o);
            np += __shfl_down_sync(0xffffffffu, np, o);
        }
        if (lane == 0) {
            atomicAdd(&g_s.part[0], pl);
            atomicAdd(&g_s.part[1], np);
            __threadfence();
            unsigned done = atomicAdd(&g_s.done, 1u);
            if (done == gridDim.x - 1) {
                float a = atomicAdd(&g_s.part[0], 0.0f);
                float b = atomicAdd(&g_s.part[1], 0.0f);
                out[0] = a / fmaxf(b, 1.0f);
            }
        }
    }
}

extern "C" void kernel_launch(void* const* d_in, const int* in_sizes, int n_in,
                              void* d_out, int out_size) {
    const float* pos = (const float*)d_in[0];
    const int*   ei  = (const int*)d_in[2];
    int N = in_sizes[0] / 2;      // node_positions: (1, N, 2)
    int E = in_sizes[2] / 2;      // edge_index: (2, E)

    // Capture-time host setup (no allocations): maximize L1 for the gather kernel.
    static bool configured = false;
    if (!configured) {
        cudaFuncSetAttribute(edge_kernel,
                             cudaFuncAttributePreferredSharedMemoryCarveout, 0);
        configured = true;
    }

    void* scratch_ptr = nullptr;
    cudaGetSymbolAddress(&scratch_ptr, g_s);
    cudaMemsetAsync(scratch_ptr, 0, sizeof(Scratch));  // captured as a memset node

    const int TB = 256;
    edge_kernel<<<(E + TB - 1) / TB, TB>>>(pos, ei, E);
    node_kernel<<<(N + TB - 1) / TB, TB>>>(N, (float*)d_out);
}